// round 4
// baseline (speedup 1.0000x reference)
#define _GNU_SOURCE 1
#include <cuda_runtime.h>
#include <cuda.h>
#include <stdint.h>
#include <dlfcn.h>

#define BATCH   64
#define NPB     16384
#define KSEL    1000
#define NCLS    80
#define NBIN    4096
#define CANDMAX 2048
#define NGROUPS 16            // 16 groups x 1024 rows = 16384 rows per batch
#define RING    3
#define GROUP_FLOATS 8192     // 4 tiles x 256 rows x 8 floats
#define GROUP_BYTES  32768

typedef unsigned long long u64;

__device__ int g_topidx[BATCH * KSEL];

// ---------------------------------------------------------------------------
// PTX helpers
// ---------------------------------------------------------------------------
__device__ __forceinline__ unsigned scvta(const void* p) {
    return (unsigned)__cvta_generic_to_shared(p);
}
__device__ __forceinline__ void mbar_init(unsigned mb, unsigned cnt) {
    asm volatile("mbarrier.init.shared.b64 [%0], %1;" :: "r"(mb), "r"(cnt) : "memory");
}
__device__ __forceinline__ void mbar_expect(unsigned mb, unsigned bytes) {
    asm volatile("mbarrier.arrive.expect_tx.shared.b64 _, [%0], %1;"
                 :: "r"(mb), "r"(bytes) : "memory");
}
__device__ __forceinline__ void mbar_wait(unsigned mb, unsigned parity) {
    unsigned done;
    asm volatile(
        "{\n\t.reg .pred p;\n\t"
        "mbarrier.try_wait.parity.acquire.cta.shared::cta.b64 p, [%1], %2;\n\t"
        "selp.b32 %0, 1, 0, p;\n\t}"
        : "=r"(done) : "r"(mb), "r"(parity) : "memory");
    if (!done) {
        asm volatile(
            "{\n\t.reg .pred P1;\n\t"
            "W_%=:\n\t"
            "mbarrier.try_wait.parity.acquire.cta.shared::cta.b64 P1, [%0], %1, 0x989680;\n\t"
            "@P1 bra.uni D_%=;\n\t"
            "bra.uni W_%=;\n\t"
            "D_%=:\n\t}"
            :: "r"(mb), "r"(parity) : "memory");
    }
}
__device__ __forceinline__ void tma_tile_2d(unsigned dst, const CUtensorMap* tmap,
                                            int row, unsigned mb) {
    asm volatile(
        "cp.async.bulk.tensor.2d.shared::cta.global.tile.mbarrier::complete_tx::bytes "
        "[%0], [%1, {%2, %3}], [%4];"
        :: "r"(dst), "l"(tmap), "r"(0), "r"(row), "r"(mb) : "memory");
}
__device__ __forceinline__ void bulk_g2s(unsigned dst, const void* src,
                                         unsigned bytes, unsigned mb) {
    asm volatile(
        "cp.async.bulk.shared::cta.global.mbarrier::complete_tx::bytes "
        "[%0], [%1], %2, [%3];"
        :: "r"(dst), "l"(src), "r"(bytes), "r"(mb) : "memory");
}
__device__ __forceinline__ void bulk_s2g(void* dst, unsigned src, unsigned bytes) {
    asm volatile(
        "cp.async.bulk.global.shared::cta.bulk_group [%0], [%1], %2;"
        :: "l"(dst), "r"(src), "r"(bytes) : "memory");
}

// ---------------------------------------------------------------------------
// threshold search over 4096-bin histogram (descending), warp-shuffle scan
// ---------------------------------------------------------------------------
__device__ __forceinline__ void find_thresh(
    const unsigned* hist, unsigned* warpsums, unsigned Kneed,
    unsigned* out_bin, unsigned* out_above, int tid)
{
    int base = NBIN - 1 - 4 * tid;
    unsigned c0 = hist[base],     c1 = hist[base - 1];
    unsigned c2 = hist[base - 2], c3 = hist[base - 3];
    unsigned tsum = c0 + c1 + c2 + c3;

    unsigned v = tsum;
    #pragma unroll
    for (int d = 1; d < 32; d <<= 1) {
        unsigned n = __shfl_up_sync(0xFFFFFFFFu, v, d);
        if ((tid & 31) >= d) v += n;
    }
    if ((tid & 31) == 31) warpsums[tid >> 5] = v;
    __syncthreads();
    if (tid < 32) {
        unsigned w = warpsums[tid];
        #pragma unroll
        for (int d = 1; d < 32; d <<= 1) {
            unsigned n = __shfl_up_sync(0xFFFFFFFFu, w, d);
            if (tid >= d) w += n;
        }
        warpsums[tid] = w;
    }
    __syncthreads();
    unsigned wpre = (tid >= 32) ? warpsums[(tid >> 5) - 1] : 0u;
    unsigned run  = wpre + v - tsum;

    if (run < Kneed && run + c0 >= Kneed) { *out_bin = (unsigned)base;     *out_above = run; }
    run += c0;
    if (run < Kneed && run + c1 >= Kneed) { *out_bin = (unsigned)base - 1; *out_above = run; }
    run += c1;
    if (run < Kneed && run + c2 >= Kneed) { *out_bin = (unsigned)base - 2; *out_above = run; }
    run += c2;
    if (run < Kneed && run + c3 >= Kneed) { *out_bin = (unsigned)base - 3; *out_above = run; }
    __syncthreads();
}

// ---------------------------------------------------------------------------
// shared select epilogue: level-1 hist must already be in `hist`, fg bits in sfg.
// ---------------------------------------------------------------------------
__device__ __forceinline__ void select_epilogue(
    unsigned* sfg, unsigned* hist, u64* cand, int b, int tid)
{
    __shared__ unsigned warpsums[32];
    __shared__ unsigned s_bin1, s_above1, s_bin2, s_above2, s_ncand;

    if (tid == 0) s_ncand = 0u;
    find_thresh(hist, warpsums, KSEL, &s_bin1, &s_above1, tid);
    unsigned bin1 = s_bin1, above1 = s_above1;

    for (int i = tid; i < NBIN; i += 1024) hist[i] = 0u;
    __syncthreads();
    #pragma unroll
    for (int q = 0; q < NGROUPS; q++) {
        unsigned u = sfg[q * 1024 + tid];
        if ((u >> 20) == bin1) atomicAdd(&hist[(u >> 8) & 0xFFFu], 1u);
    }
    __syncthreads();
    find_thresh(hist, warpsums, KSEL - above1, &s_bin2, &s_above2, tid);
    unsigned t24 = (bin1 << 12) | s_bin2;

    // collect: key = (bits<<32) | (NPB-1-i) -> desc key == value desc, index asc
    #pragma unroll
    for (int q = 0; q < NGROUPS; q++) {
        int i = q * 1024 + tid;
        unsigned u = sfg[i];
        if ((u >> 8) >= t24) {
            unsigned p = atomicAdd(&s_ncand, 1u);
            if (p < CANDMAX)
                cand[p] = ((u64)u << 32) | (u64)(unsigned)(NPB - 1 - i);
        }
    }
    __syncthreads();
    unsigned nc = s_ncand < CANDMAX ? s_ncand : CANDMAX;
    unsigned SORT = (nc <= 1024u) ? 1024u : 2048u;
    for (unsigned i = tid; i < SORT; i += 1024)
        if (i >= nc) cand[i] = 0ull;

    // bitonic sort descending (dynamic size)
    for (unsigned k = 2; k <= SORT; k <<= 1) {
        for (unsigned j = k >> 1; j > 0; j >>= 1) {
            __syncthreads();
            if ((unsigned)tid < (SORT >> 1)) {
                unsigned mask = j - 1u;
                unsigned i = (((unsigned)tid & ~mask) << 1) | ((unsigned)tid & mask);
                unsigned p = i | j;
                u64 a = cand[i], c = cand[p];
                bool desc = ((i & k) == 0u);
                if (desc ? (a < c) : (a > c)) { cand[i] = c; cand[p] = a; }
            }
        }
    }
    __syncthreads();

    if (tid < KSEL) {
        unsigned ilocal = (NPB - 1u) - (unsigned)(cand[tid] & 0xFFFFull);
        g_topidx[b * KSEL + tid] = (int)ilocal;
    }
}

// ---------------------------------------------------------------------------
// Fused extract+select (TMA streaming). One CTA per batch.
// smem: ring buf 96KB | sfg 64KB | hist 16KB | cand 16KB = 192KB dynamic.
// ---------------------------------------------------------------------------
extern __shared__ unsigned char smem_raw[];

__global__ void __launch_bounds__(1024, 1)
fused_select_tma(const __grid_constant__ CUtensorMap tmap)
{
    float*    buf  = (float*)smem_raw;
    unsigned* sfg  = (unsigned*)(smem_raw + RING * GROUP_BYTES);
    unsigned* hist = sfg + NPB;
    u64*      cand = (u64*)(hist + NBIN);
    __shared__ alignas(8) u64 mbar[RING];

    const int b   = blockIdx.x;
    const int tid = threadIdx.x;

    for (int i = tid; i < NBIN; i += 1024) hist[i] = 0u;
    if (tid == 0)
        for (int s = 0; s < RING; s++) mbar_init(scvta(&mbar[s]), 1u);
    __syncthreads();

    if (tid == 0) {
        #pragma unroll
        for (int g = 0; g < RING; g++) {
            unsigned mb = scvta(&mbar[g]);
            mbar_expect(mb, GROUP_BYTES);
            unsigned dst = scvta(buf) + g * GROUP_BYTES;
            int rowbase = b * NPB + g * 1024;
            #pragma unroll
            for (int t = 0; t < 4; t++)
                tma_tile_2d(dst + t * 8192, &tmap, rowbase + t * 256, mb);
        }
    }

    for (int g = 0; g < NGROUPS; g++) {
        int s = g % RING;
        unsigned parity = (unsigned)((g / RING) & 1);
        mbar_wait(scvta(&mbar[s]), parity);

        float v = buf[s * GROUP_FLOATS + tid * 8];   // col 0 of row (g*1024+tid)
        unsigned u = __float_as_uint(1.0f - v);
        sfg[g * 1024 + tid] = u;
        atomicAdd(&hist[u >> 20], 1u);
        __syncthreads();                              // slot fully consumed

        if (tid == 0 && g + RING < NGROUPS) {
            int gn = g + RING;
            unsigned mb = scvta(&mbar[s]);
            mbar_expect(mb, GROUP_BYTES);
            unsigned dst = scvta(buf) + s * GROUP_BYTES;
            int rowbase = b * NPB + gn * 1024;
            #pragma unroll
            for (int t = 0; t < 4; t++)
                tma_tile_2d(dst + t * 8192, &tmap, rowbase + t * 256, mb);
        }
    }
    __syncthreads();

    select_epilogue(sfg, hist, cand, b, tid);
}

// Fallback (no driver tensormap encode): strided LDG streaming, same epilogue.
__global__ void __launch_bounds__(1024, 1)
fused_select_ldg(const float* __restrict__ scores)
{
    unsigned* sfg  = (unsigned*)(smem_raw + RING * GROUP_BYTES);
    unsigned* hist = sfg + NPB;
    u64*      cand = (u64*)(hist + NBIN);

    const int b   = blockIdx.x;
    const int tid = threadIdx.x;

    for (int i = tid; i < NBIN; i += 1024) hist[i] = 0u;
    __syncthreads();

    #pragma unroll
    for (int q = 0; q < NGROUPS; q++) {
        int i = q * 1024 + tid;
        float s = __ldg(scores + (size_t)(b * NPB + i) * NCLS);
        unsigned u = __float_as_uint(1.0f - s);
        sfg[i] = u;
        atomicAdd(&hist[u >> 20], 1u);
    }
    __syncthreads();

    select_epilogue(sfg, hist, cand, b, tid);
}

// ---------------------------------------------------------------------------
// Gather via cp.async.bulk: 64 rows per CTA. Loads 64x320B score rows and
// 64x16B box rows into smem, then two contiguous bulk stores to out.
// out layout (f32): scores[64000*80] | batch_idx[64000] | boxes[64000*4]
// ---------------------------------------------------------------------------
#define BI_BYTE_OFF  20480000u   // 64000*80*4
#define BX_BYTE_OFF  20736000u   // + 64000*4

__global__ void __launch_bounds__(128)
gather_bulk(const float* __restrict__ scores,
            const float* __restrict__ boxes,
            float* __restrict__ out)
{
    __shared__ alignas(128) unsigned char sbuf[64 * 320 + 64 * 16];  // 21504B
    __shared__ alignas(8) u64 mbar;

    const int tid = threadIdx.x;
    const int r0  = blockIdx.x * 64;
    unsigned mb = scvta(&mbar);

    if (tid == 0) mbar_init(mb, 1u);
    __syncthreads();
    if (tid == 0) mbar_expect(mb, 21504u);
    __syncthreads();

    if (tid < 64) {
        int row = r0 + tid;
        int bb  = row / KSEL;
        int il  = __ldg(&g_topidx[row]);
        size_t g = (size_t)bb * NPB + (size_t)il;
        bulk_g2s(scvta(sbuf) + tid * 320, scores + g * NCLS, 320u, mb);
    } else {
        int row = r0 + tid - 64;
        int bb  = row / KSEL;
        int il  = __ldg(&g_topidx[row]);
        size_t g = (size_t)bb * NPB + (size_t)il;
        bulk_g2s(scvta(sbuf) + 20480 + (tid - 64) * 16, boxes + g * 4, 16u, mb);
        // batch index: deterministic, no dependency on loads
        *(float*)((char*)out + BI_BYTE_OFF + (size_t)row * 4) = (float)bb;
    }

    mbar_wait(mb, 0u);

    if (tid == 0) {
        asm volatile("fence.proxy.async.shared::cta;" ::: "memory");
        bulk_s2g((char*)out + (size_t)r0 * 320, scvta(sbuf), 20480u);
        bulk_s2g((char*)out + BX_BYTE_OFF + (size_t)r0 * 16, scvta(sbuf) + 20480, 1024u);
        asm volatile("cp.async.bulk.commit_group;" ::: "memory");
        asm volatile("cp.async.bulk.wait_group 0;" ::: "memory");
    }
}

// ---------------------------------------------------------------------------
typedef CUresult (*EncodeTiledFn)(
    CUtensorMap*, CUtensorMapDataType, cuuint32_t, void*,
    const cuuint64_t*, const cuuint64_t*, const cuuint32_t*, const cuuint32_t*,
    CUtensorMapInterleave, CUtensorMapSwizzle, CUtensorMapL2promotion,
    CUtensorMapFloatOOBfill);

extern "C" void kernel_launch(void* const* d_in, const int* in_sizes, int n_in,
                              void* d_out, int out_size)
{
    const float* scores = (const float*)d_in[0];
    const float* boxes  = (const float*)d_in[2];
    float* out = (float*)d_out;

    const int smem_fused = RING * GROUP_BYTES + NPB * 4 + NBIN * 4 + CANDMAX * 8; // 196608
    static int configured = -1;
    if (configured < 0) {
        cudaFuncSetAttribute(fused_select_tma, cudaFuncAttributeMaxDynamicSharedMemorySize, smem_fused);
        cudaFuncSetAttribute(fused_select_ldg, cudaFuncAttributeMaxDynamicSharedMemorySize, smem_fused);
        configured = 1;
    }

    bool tma_ok = false;
    alignas(64) CUtensorMap tmap;
    EncodeTiledFn enc = (EncodeTiledFn)dlsym(RTLD_DEFAULT, "cuTensorMapEncodeTiled");
    if (enc) {
        cuuint64_t dims[2]    = { (cuuint64_t)NCLS, (cuuint64_t)(BATCH * NPB) };
        cuuint64_t strides[1] = { (cuuint64_t)NCLS * sizeof(float) };   // 320 B
        cuuint32_t box[2]     = { 8, 256 };                             // 32 B x 256 rows
        cuuint32_t es[2]      = { 1, 1 };
        CUresult r = enc(&tmap, CU_TENSOR_MAP_DATA_TYPE_FLOAT32, 2, (void*)scores,
                         dims, strides, box, es,
                         CU_TENSOR_MAP_INTERLEAVE_NONE, CU_TENSOR_MAP_SWIZZLE_NONE,
                         CU_TENSOR_MAP_L2_PROMOTION_NONE, CU_TENSOR_MAP_FLOAT_OOB_FILL_NONE);
        tma_ok = (r == CUDA_SUCCESS);
    }

    if (tma_ok)
        fused_select_tma<<<BATCH, 1024, smem_fused>>>(tmap);
    else
        fused_select_ldg<<<BATCH, 1024, smem_fused>>>(scores);

    gather_bulk<<<(BATCH * KSEL) / 64, 128>>>(scores, boxes, out);
}

// round 5
// speedup vs baseline: 1.0752x; 1.0752x over previous
#include <cuda_runtime.h>
#include <stdint.h>

#define BATCH   64
#define NPB     16384
#define KSEL    1000
#define NCLS    80
#define NBIN    4096
#define CANDMAX 2048

typedef unsigned long long u64;

__device__ unsigned g_fg[BATCH * NPB];    // fg float bits per row (4 MB)

// out layout (f32): scores[64000*80] | batch_idx[64000] | boxes[64000*4]
#define BI_FOFF 5120000u
#define BX_FOFF 5184000u

// ---------------------------------------------------------------------------
// Kernel A: strided column-0 read, coalesced write of fg bits. (R2-proven)
// ---------------------------------------------------------------------------
__global__ void __launch_bounds__(256)
extract_kernel(const float* __restrict__ scores)
{
    int base = blockIdx.x * 2048;
    int tid  = threadIdx.x;
    #pragma unroll 8
    for (int k = 0; k < 8; k++) {
        int r = base + k * 256 + tid;
        float s = __ldg(scores + (size_t)r * NCLS);
        g_fg[r] = __float_as_uint(1.0f - s);   // positive floats: bits order-preserving
    }
}

// ---------------------------------------------------------------------------
// threshold search over 4096-bin histogram (descending), warp-shuffle scan
// ---------------------------------------------------------------------------
__device__ __forceinline__ void find_thresh(
    const unsigned* hist, unsigned* warpsums, unsigned Kneed,
    unsigned* out_bin, unsigned* out_above, int tid)
{
    int base = NBIN - 1 - 4 * tid;
    unsigned c0 = hist[base],     c1 = hist[base - 1];
    unsigned c2 = hist[base - 2], c3 = hist[base - 3];
    unsigned tsum = c0 + c1 + c2 + c3;

    unsigned v = tsum;
    #pragma unroll
    for (int d = 1; d < 32; d <<= 1) {
        unsigned n = __shfl_up_sync(0xFFFFFFFFu, v, d);
        if ((tid & 31) >= d) v += n;
    }
    if ((tid & 31) == 31) warpsums[tid >> 5] = v;
    __syncthreads();
    if (tid < 32) {
        unsigned w = warpsums[tid];
        #pragma unroll
        for (int d = 1; d < 32; d <<= 1) {
            unsigned n = __shfl_up_sync(0xFFFFFFFFu, w, d);
            if (tid >= d) w += n;
        }
        warpsums[tid] = w;
    }
    __syncthreads();
    unsigned wpre = (tid >= 32) ? warpsums[(tid >> 5) - 1] : 0u;
    unsigned run  = wpre + v - tsum;               // count in strictly-higher bins

    if (run < Kneed && run + c0 >= Kneed) { *out_bin = (unsigned)base;     *out_above = run; }
    run += c0;
    if (run < Kneed && run + c1 >= Kneed) { *out_bin = (unsigned)base - 1; *out_above = run; }
    run += c1;
    if (run < Kneed && run + c2 >= Kneed) { *out_bin = (unsigned)base - 2; *out_above = run; }
    run += c2;
    if (run < Kneed && run + c3 >= Kneed) { *out_bin = (unsigned)base - 3; *out_above = run; }
    __syncthreads();
}

// ---------------------------------------------------------------------------
// Kernel B: per-batch top-K selection + in-kernel gather. One CTA per batch.
// ---------------------------------------------------------------------------
__global__ void __launch_bounds__(1024, 1)
select_gather_kernel(const float* __restrict__ scores,
                     const float* __restrict__ boxes,
                     float* __restrict__ out)
{
    __shared__ unsigned sh_hist[NBIN];      // 16 KB
    __shared__ u64      sh_cand[CANDMAX];   // 16 KB
    __shared__ unsigned sh_warpsums[32];
    __shared__ unsigned s_bin1, s_above1, s_bin2, s_above2, s_ncand;

    const int b    = blockIdx.x;
    const int tid  = threadIdx.x;
    const int lane = tid & 31;

    // ---- load 16 fg values into registers (coalesced uint4) ----
    unsigned v[16];
    const uint4* src = (const uint4*)(g_fg + b * NPB);
    #pragma unroll
    for (int c = 0; c < 4; c++) {
        uint4 x = __ldg(src + c * 1024 + tid);
        v[c * 4 + 0] = x.x; v[c * 4 + 1] = x.y;
        v[c * 4 + 2] = x.z; v[c * 4 + 3] = x.w;
    }

    for (int i = tid; i < NBIN; i += 1024) sh_hist[i] = 0u;
    if (tid == 0) s_ncand = 0u;
    __syncthreads();

    // ---- level-1 histogram: top 12 bits ----
    #pragma unroll
    for (int q = 0; q < 16; q++)
        atomicAdd(&sh_hist[v[q] >> 20], 1u);
    __syncthreads();
    find_thresh(sh_hist, sh_warpsums, KSEL, &s_bin1, &s_above1, tid);
    unsigned bin1 = s_bin1, above1 = s_above1;

    // ---- level-2 histogram: next 12 bits within bin1 ----
    for (int i = tid; i < NBIN; i += 1024) sh_hist[i] = 0u;
    __syncthreads();
    #pragma unroll
    for (int q = 0; q < 16; q++)
        if ((v[q] >> 20) == bin1) atomicAdd(&sh_hist[(v[q] >> 8) & 0xFFFu], 1u);
    __syncthreads();
    find_thresh(sh_hist, sh_warpsums, KSEL - above1, &s_bin2, &s_above2, tid);
    unsigned t24 = (bin1 << 12) | s_bin2;

    // ---- collect candidates, warp-aggregated counter ----
    // key = (bits << 32) | (NPB-1-i): desc key == value desc, index asc (jax tie-break)
    #pragma unroll
    for (int c = 0; c < 4; c++) {
        #pragma unroll
        for (int q = 0; q < 4; q++) {
            unsigned u = v[c * 4 + q];
            bool pred = ((u >> 8) >= t24);
            unsigned mask = __ballot_sync(0xFFFFFFFFu, pred);
            if (mask) {
                int leader = __ffs(mask) - 1;
                unsigned basep = 0;
                if (lane == leader) basep = atomicAdd(&s_ncand, (unsigned)__popc(mask));
                basep = __shfl_sync(0xFFFFFFFFu, basep, leader);
                if (pred) {
                    unsigned off = basep + (unsigned)__popc(mask & ((1u << lane) - 1u));
                    if (off < CANDMAX) {
                        int i = (c * 1024 + tid) * 4 + q;
                        sh_cand[off] = ((u64)u << 32) | (u64)(unsigned)(NPB - 1 - i);
                    }
                }
            }
        }
    }
    __syncthreads();
    unsigned nc = s_ncand < CANDMAX ? s_ncand : CANDMAX;
    unsigned SORT = (nc <= 1024u) ? 1024u : 2048u;
    for (unsigned i = tid; i < SORT; i += 1024)
        if (i >= nc) sh_cand[i] = 0ull;

    // ---- bitonic sort descending (dynamic size) ----
    for (unsigned k = 2; k <= SORT; k <<= 1) {
        for (unsigned j = k >> 1; j > 0; j >>= 1) {
            __syncthreads();
            if ((unsigned)tid < (SORT >> 1)) {
                unsigned mask = j - 1u;
                unsigned i = (((unsigned)tid & ~mask) << 1) | ((unsigned)tid & mask);
                unsigned p = i | j;
                u64 a = sh_cand[i], c = sh_cand[p];
                bool desc = ((i & k) == 0u);
                if (desc ? (a < c) : (a > c)) { sh_cand[i] = c; sh_cand[p] = a; }
            }
        }
    }
    __syncthreads();

    // ---- in-kernel gather ----
    // scores: 8 threads per output row; thread q handles float4 chunks {q, q+8, 16+q(<20)}
    // warp covers 4 rows -> each warp-wide LDG.128 reads 4 x 128B contiguous segments.
    const int q   = tid & 7;
    const int rw  = tid >> 3;                    // 0..127 row-within-iteration
    #pragma unroll 1
    for (int it = 0; it < 8; it++) {
        int row = it * 128 + rw;                 // rank
        if (row < KSEL) {
            unsigned il = (NPB - 1u) - (unsigned)(sh_cand[row] & 0xFFFFull);
            const float4* s4 = (const float4*)(scores + ((size_t)b * NPB + il) * NCLS);
            float4*       d4 = (float4*)(out + ((size_t)b * KSEL + row) * NCLS);
            float4 a0 = __ldg(s4 + q);
            float4 a1 = __ldg(s4 + q + 8);
            float4 a2;
            if (q < 4) a2 = __ldg(s4 + 16 + q);
            d4[q]     = a0;
            d4[q + 8] = a1;
            if (q < 4) d4[16 + q] = a2;
        }
    }
    // boxes + batch index: one thread per row
    if (tid < KSEL) {
        unsigned il = (NPB - 1u) - (unsigned)(sh_cand[tid] & 0xFFFFull);
        size_t g = (size_t)b * NPB + il;
        size_t r = (size_t)b * KSEL + (size_t)tid;
        float4 bx = __ldg((const float4*)(boxes + g * 4));
        *(float4*)(out + BX_FOFF + r * 4) = bx;
        out[BI_FOFF + r] = (float)b;
    }
}

extern "C" void kernel_launch(void* const* d_in, const int* in_sizes, int n_in,
                              void* d_out, int out_size)
{
    const float* scores = (const float*)d_in[0];
    const float* boxes  = (const float*)d_in[2];
    float* out = (float*)d_out;

    extract_kernel<<<(BATCH * NPB) / 2048, 256>>>(scores);
    select_gather_kernel<<<BATCH, 1024>>>(scores, boxes, out);
}

// round 7
// speedup vs baseline: 1.1183x; 1.0400x over previous
#include <cuda_runtime.h>
#include <stdint.h>

#define BATCH   64
#define NPB     16384
#define KSEL    1000
#define NCLS    80
#define NBIN    4096
#define CANDMAX 2048

typedef unsigned long long u64;

// out layout (f32): scores[64000*80] | batch_idx[64000] | boxes[64000*4]
#define BI_FOFF 5120000u
#define BX_FOFF 5184000u

// ---------------------------------------------------------------------------
// threshold search over 4096-bin histogram (descending), warp-shuffle scan
// ---------------------------------------------------------------------------
__device__ __forceinline__ void find_thresh(
    const unsigned* hist, unsigned* warpsums, unsigned Kneed,
    unsigned* out_bin, unsigned* out_above, int tid)
{
    int base = NBIN - 1 - 4 * tid;
    unsigned c0 = hist[base],     c1 = hist[base - 1];
    unsigned c2 = hist[base - 2], c3 = hist[base - 3];
    unsigned tsum = c0 + c1 + c2 + c3;

    unsigned v = tsum;
    #pragma unroll
    for (int d = 1; d < 32; d <<= 1) {
        unsigned n = __shfl_up_sync(0xFFFFFFFFu, v, d);
        if ((tid & 31) >= d) v += n;
    }
    if ((tid & 31) == 31) warpsums[tid >> 5] = v;
    __syncthreads();
    if (tid < 32) {
        unsigned w = warpsums[tid];
        #pragma unroll
        for (int d = 1; d < 32; d <<= 1) {
            unsigned n = __shfl_up_sync(0xFFFFFFFFu, w, d);
            if (tid >= d) w += n;
        }
        warpsums[tid] = w;
    }
    __syncthreads();
    unsigned wpre = (tid >= 32) ? warpsums[(tid >> 5) - 1] : 0u;
    unsigned run  = wpre + v - tsum;               // count in strictly-higher bins

    if (run < Kneed && run + c0 >= Kneed) { *out_bin = (unsigned)base;     *out_above = run; }
    run += c0;
    if (run < Kneed && run + c1 >= Kneed) { *out_bin = (unsigned)base - 1; *out_above = run; }
    run += c1;
    if (run < Kneed && run + c2 >= Kneed) { *out_bin = (unsigned)base - 2; *out_above = run; }
    run += c2;
    if (run < Kneed && run + c3 >= Kneed) { *out_bin = (unsigned)base - 3; *out_above = run; }
    __syncthreads();
}

// ---------------------------------------------------------------------------
// Fully fused: extract (own batch, registers) -> radix top-K -> gather.
// One CTA per batch, 1024 threads.
// ---------------------------------------------------------------------------
__global__ void __launch_bounds__(1024, 1)
fused_kernel(const float* __restrict__ scores,
             const float* __restrict__ boxes,
             float* __restrict__ out)
{
    __shared__ unsigned sh_hist[NBIN];      // 16 KB
    __shared__ u64      sh_cand[CANDMAX];   // 16 KB
    __shared__ unsigned sh_warpsums[32];
    __shared__ unsigned s_bin1, s_above1, s_bin2, s_above2, s_ncand;

    const int b    = blockIdx.x;
    const int tid  = threadIdx.x;
    const int lane = tid & 31;

    // ---- extract: 16 independent strided column-0 loads (MLP 16) ----
    // thread tid owns rows { q*1024 + tid : q in [0,16) } of this batch.
    const float* colbase = scores + (size_t)b * NPB * NCLS;
    float raw[16];
    #pragma unroll
    for (int q = 0; q < 16; q++)
        raw[q] = __ldg(colbase + (size_t)(q * 1024 + tid) * NCLS);

    // hist zeroing overlaps the outstanding loads
    for (int i = tid; i < NBIN; i += 1024) sh_hist[i] = 0u;
    if (tid == 0) s_ncand = 0u;
    __syncthreads();

    unsigned v[16];
    #pragma unroll
    for (int q = 0; q < 16; q++)
        v[q] = __float_as_uint(1.0f - raw[q]);   // positive floats: bits order-preserving

    // ---- level-1 histogram: top 12 bits ----
    #pragma unroll
    for (int q = 0; q < 16; q++)
        atomicAdd(&sh_hist[v[q] >> 20], 1u);
    __syncthreads();
    find_thresh(sh_hist, sh_warpsums, KSEL, &s_bin1, &s_above1, tid);
    unsigned bin1 = s_bin1, above1 = s_above1;

    // ---- level-2 histogram: next 12 bits within bin1 ----
    for (int i = tid; i < NBIN; i += 1024) sh_hist[i] = 0u;
    __syncthreads();
    #pragma unroll
    for (int q = 0; q < 16; q++)
        if ((v[q] >> 20) == bin1) atomicAdd(&sh_hist[(v[q] >> 8) & 0xFFFu], 1u);
    __syncthreads();
    find_thresh(sh_hist, sh_warpsums, KSEL - above1, &s_bin2, &s_above2, tid);
    unsigned t24 = (bin1 << 12) | s_bin2;

    // ---- collect candidates, warp-aggregated counter ----
    // key = (bits << 32) | (NPB-1-i): desc key == value desc, index asc (jax tie-break)
    #pragma unroll
    for (int q = 0; q < 16; q++) {
        unsigned u = v[q];
        bool pred = ((u >> 8) >= t24);
        unsigned mask = __ballot_sync(0xFFFFFFFFu, pred);
        if (mask) {
            int leader = __ffs(mask) - 1;
            unsigned basep = 0;
            if (lane == leader) basep = atomicAdd(&s_ncand, (unsigned)__popc(mask));
            basep = __shfl_sync(0xFFFFFFFFu, basep, leader);
            if (pred) {
                unsigned off = basep + (unsigned)__popc(mask & ((1u << lane) - 1u));
                if (off < CANDMAX) {
                    int i = q * 1024 + tid;
                    sh_cand[off] = ((u64)u << 32) | (u64)(unsigned)(NPB - 1 - i);
                }
            }
        }
    }
    __syncthreads();
    unsigned nc = s_ncand < CANDMAX ? s_ncand : CANDMAX;
    unsigned SORT = (nc <= 1024u) ? 1024u : 2048u;
    for (unsigned i = tid; i < SORT; i += 1024)
        if (i >= nc) sh_cand[i] = 0ull;

    // ---- bitonic sort descending (dynamic size) ----
    for (unsigned k = 2; k <= SORT; k <<= 1) {
        for (unsigned j = k >> 1; j > 0; j >>= 1) {
            __syncthreads();
            if ((unsigned)tid < (SORT >> 1)) {
                unsigned mask = j - 1u;
                unsigned i = (((unsigned)tid & ~mask) << 1) | ((unsigned)tid & mask);
                unsigned p = i | j;
                u64 a = sh_cand[i], c = sh_cand[p];
                bool desc = ((i & k) == 0u);
                if (desc ? (a < c) : (a > c)) { sh_cand[i] = c; sh_cand[p] = a; }
            }
        }
    }
    __syncthreads();

    // ---- gather: 2 rows per iteration (MLP ~6), 8 threads per row ----
    const int q  = tid & 7;
    const int rw = tid >> 3;                      // 0..127
    #pragma unroll 1
    for (int it = 0; it < 8; it += 2) {
        int rowA = it * 128 + rw;                 // always < 1000 (max 895)
        int rowB = rowA + 128;                    // may exceed 999 on last pair
        bool vB = rowB < KSEL;
        unsigned ilA = (NPB - 1u) - (unsigned)(sh_cand[rowA] & 0xFFFFull);
        unsigned ilB = (NPB - 1u) - (unsigned)(sh_cand[vB ? rowB : rowA] & 0xFFFFull);
        const float4* sA = (const float4*)(scores + ((size_t)b * NPB + ilA) * NCLS);
        const float4* sB = (const float4*)(scores + ((size_t)b * NPB + ilB) * NCLS);
        float4 a0 = __ldg(sA + q);
        float4 b0 = __ldg(sB + q);
        float4 a1 = __ldg(sA + q + 8);
        float4 b1 = __ldg(sB + q + 8);
        float4 a2, b2;
        if (q < 4) { a2 = __ldg(sA + 16 + q); b2 = __ldg(sB + 16 + q); }

        float4* dA = (float4*)(out + ((size_t)b * KSEL + rowA) * NCLS);
        dA[q]     = a0;
        dA[q + 8] = a1;
        if (q < 4) dA[16 + q] = a2;
        if (vB) {
            float4* dB = (float4*)(out + ((size_t)b * KSEL + rowB) * NCLS);
            dB[q]     = b0;
            dB[q + 8] = b1;
            if (q < 4) dB[16 + q] = b2;
        }
    }
    // boxes + batch index: one thread per row
    if (tid < KSEL) {
        unsigned il = (NPB - 1u) - (unsigned)(sh_cand[tid] & 0xFFFFull);
        size_t g = (size_t)b * NPB + il;
        size_t r = (size_t)b * KSEL + (size_t)tid;
        float4 bx = __ldg((const float4*)(boxes + g * 4));
        *(float4*)(out + BX_FOFF + r * 4) = bx;
        out[BI_FOFF + r] = (float)b;
    }
}

extern "C" void kernel_launch(void* const* d_in, const int* in_sizes, int n_in,
                              void* d_out, int out_size)
{
    const float* scores = (const float*)d_in[0];
    const float* boxes  = (const float*)d_in[2];
    float* out = (float*)d_out;

    fused_kernel<<<BATCH, 1024>>>(scores, boxes, out);
}

// round 9
// speedup vs baseline: 1.1695x; 1.0457x over previous
#include <cuda_runtime.h>
#include <stdint.h>

#define BATCH   64
#define NPB     16384
#define HALF    8192
#define KSEL    1000
#define NCLS    80
#define NBIN    4096
#define CANDMAX 2048

typedef unsigned long long u64;

// sorted top-1000 keys per half-batch (key = bits<<32 | (NPB-1-idx))
__device__ u64 g_cand[2 * BATCH][KSEL];

// out layout (f32): scores[64000*80] | batch_idx[64000] | boxes[64000*4]
#define BI_FOFF 5120000u
#define BX_FOFF 5184000u

// ---------------------------------------------------------------------------
// threshold search over 4096-bin histogram (descending), warp-shuffle scan
// ---------------------------------------------------------------------------
__device__ __forceinline__ void find_thresh(
    const unsigned* hist, unsigned* warpsums, unsigned Kneed,
    unsigned* out_bin, unsigned* out_above, int tid)
{
    int base = NBIN - 1 - 4 * tid;
    unsigned c0 = hist[base],     c1 = hist[base - 1];
    unsigned c2 = hist[base - 2], c3 = hist[base - 3];
    unsigned tsum = c0 + c1 + c2 + c3;

    unsigned v = tsum;
    #pragma unroll
    for (int d = 1; d < 32; d <<= 1) {
        unsigned n = __shfl_up_sync(0xFFFFFFFFu, v, d);
        if ((tid & 31) >= d) v += n;
    }
    if ((tid & 31) == 31) warpsums[tid >> 5] = v;
    __syncthreads();
    if (tid < 32) {
        unsigned w = warpsums[tid];
        #pragma unroll
        for (int d = 1; d < 32; d <<= 1) {
            unsigned n = __shfl_up_sync(0xFFFFFFFFu, w, d);
            if (tid >= d) w += n;
        }
        warpsums[tid] = w;
    }
    __syncthreads();
    unsigned wpre = (tid >= 32) ? warpsums[(tid >> 5) - 1] : 0u;
    unsigned run  = wpre + v - tsum;               // count in strictly-higher bins

    if (run < Kneed && run + c0 >= Kneed) { *out_bin = (unsigned)base;     *out_above = run; }
    run += c0;
    if (run < Kneed && run + c1 >= Kneed) { *out_bin = (unsigned)base - 1; *out_above = run; }
    run += c1;
    if (run < Kneed && run + c2 >= Kneed) { *out_bin = (unsigned)base - 2; *out_above = run; }
    run += c2;
    if (run < Kneed && run + c3 >= Kneed) { *out_bin = (unsigned)base - 3; *out_above = run; }
    __syncthreads();
}

// ---------------------------------------------------------------------------
// Kernel 1: one CTA per HALF-batch (128 CTAs). Extract 8192 strided col-0
// values, select half's top-1000 (2-level radix + bitonic), write sorted list.
// ---------------------------------------------------------------------------
__global__ void __launch_bounds__(1024, 1)
half_select_kernel(const float* __restrict__ scores)
{
    __shared__ unsigned sh_hist[NBIN];      // 16 KB
    __shared__ u64      sh_cand[CANDMAX];   // 16 KB
    __shared__ unsigned sh_warpsums[32];
    __shared__ unsigned s_bin1, s_above1, s_bin2, s_above2, s_ncand;

    const int hb   = blockIdx.x;            // half-batch id [0,128)
    const int b    = hb >> 1;
    const int rk   = hb & 1;
    const int tid  = threadIdx.x;
    const int lane = tid & 31;

    // ---- extract: 8 independent strided column-0 loads ----
    const float* colbase = scores + ((size_t)b * NPB + (size_t)rk * HALF) * NCLS;
    float raw[8];
    #pragma unroll
    for (int q = 0; q < 8; q++)
        raw[q] = __ldg(colbase + (size_t)(q * 1024 + tid) * NCLS);

    for (int i = tid; i < NBIN; i += 1024) sh_hist[i] = 0u;
    if (tid == 0) s_ncand = 0u;
    __syncthreads();

    unsigned v[8];
    #pragma unroll
    for (int q = 0; q < 8; q++)
        v[q] = __float_as_uint(1.0f - raw[q]);   // positive floats: bits order-preserving

    // ---- level-1 histogram ----
    #pragma unroll
    for (int q = 0; q < 8; q++)
        atomicAdd(&sh_hist[v[q] >> 20], 1u);
    __syncthreads();
    find_thresh(sh_hist, sh_warpsums, KSEL, &s_bin1, &s_above1, tid);
    unsigned bin1 = s_bin1, above1 = s_above1;

    // ---- level-2 histogram within bin1 ----
    for (int i = tid; i < NBIN; i += 1024) sh_hist[i] = 0u;
    __syncthreads();
    #pragma unroll
    for (int q = 0; q < 8; q++)
        if ((v[q] >> 20) == bin1) atomicAdd(&sh_hist[(v[q] >> 8) & 0xFFFu], 1u);
    __syncthreads();
    find_thresh(sh_hist, sh_warpsums, KSEL - above1, &s_bin2, &s_above2, tid);
    unsigned t24 = (bin1 << 12) | s_bin2;

    // ---- collect candidates (warp-aggregated) ----
    // key = (bits<<32) | (NPB-1-idx_in_batch): desc key == value desc, index asc
    #pragma unroll
    for (int q = 0; q < 8; q++) {
        unsigned u = v[q];
        bool pred = ((u >> 8) >= t24);
        unsigned mask = __ballot_sync(0xFFFFFFFFu, pred);
        if (mask) {
            int leader = __ffs(mask) - 1;
            unsigned basep = 0;
            if (lane == leader) basep = atomicAdd(&s_ncand, (unsigned)__popc(mask));
            basep = __shfl_sync(0xFFFFFFFFu, basep, leader);
            if (pred) {
                unsigned off = basep + (unsigned)__popc(mask & ((1u << lane) - 1u));
                if (off < CANDMAX) {
                    int idx = rk * HALF + q * 1024 + tid;     // index within batch
                    sh_cand[off] = ((u64)u << 32) | (u64)(unsigned)(NPB - 1 - idx);
                }
            }
        }
    }
    __syncthreads();
    unsigned nc = s_ncand < CANDMAX ? s_ncand : CANDMAX;
    unsigned SORT = (nc <= 1024u) ? 1024u : 2048u;
    for (unsigned i = tid; i < SORT; i += 1024)
        if (i >= nc) sh_cand[i] = 0ull;

    // ---- bitonic sort descending ----
    for (unsigned k = 2; k <= SORT; k <<= 1) {
        for (unsigned j = k >> 1; j > 0; j >>= 1) {
            __syncthreads();
            if ((unsigned)tid < (SORT >> 1)) {
                unsigned mask = j - 1u;
                unsigned i = (((unsigned)tid & ~mask) << 1) | ((unsigned)tid & mask);
                unsigned p = i | j;
                u64 a = sh_cand[i], c = sh_cand[p];
                bool desc = ((i & k) == 0u);
                if (desc ? (a < c) : (a > c)) { sh_cand[i] = c; sh_cand[p] = a; }
            }
        }
    }
    __syncthreads();

    // ---- write sorted top-1000 for this half ----
    if (tid < KSEL) g_cand[hb][tid] = sh_cand[tid];
}

// ---------------------------------------------------------------------------
// Kernel 2: 2 CTAs per batch (128 CTAs). Merge the two sorted lists by
// binary-search ranking (exact, keys unique), then gather 500 rows each.
// ---------------------------------------------------------------------------
__device__ __forceinline__ unsigned count_greater(const u64* arr, u64 key)
{
    unsigned lo = 0, hi = KSEL;
    #pragma unroll
    for (int s = 0; s < 10; s++) {            // 2^10 = 1024 >= 1000
        if (lo < hi) {
            unsigned mid = (lo + hi) >> 1;
            if (arr[mid] > key) lo = mid + 1; else hi = mid;
        }
    }
    return lo;
}

__global__ void __launch_bounds__(1024, 1)
merge_gather_kernel(const float* __restrict__ scores,
                    const float* __restrict__ boxes,
                    float* __restrict__ out)
{
    __shared__ u64      shA[KSEL];            // 8 KB
    __shared__ u64      shB[KSEL];            // 8 KB
    __shared__ unsigned sh_idx[KSEL];         // 4 KB: rank -> local row index

    const int b    = blockIdx.x >> 1;
    const int part = blockIdx.x & 1;
    const int tid  = threadIdx.x;

    if (tid < KSEL) {
        shA[tid] = __ldg(&g_cand[2 * b][tid]);
        shB[tid] = __ldg(&g_cand[2 * b + 1][tid]);
    }
    __syncthreads();

    if (tid < KSEL) {
        u64 kA = shA[tid];
        unsigned rA = (unsigned)tid + count_greater(shB, kA);
        if (rA < KSEL)
            sh_idx[rA] = (NPB - 1u) - (unsigned)(kA & 0xFFFFull);
        u64 kB = shB[tid];
        unsigned rB = (unsigned)tid + count_greater(shA, kB);
        if (rB < KSEL)
            sh_idx[rB] = (NPB - 1u) - (unsigned)(kB & 0xFFFFull);
    }
    __syncthreads();

    // ---- gather ranks [part*500, part*500+500) ----
    const int rbase = part * 500;
    const int q  = tid & 7;                   // 8 threads per row
    const int rw = tid >> 3;                  // 0..127
    #pragma unroll 1
    for (int it = 0; it < 4; it += 2) {
        int lA = it * 128 + rw;               // 0..127 / 256..383: always < 500
        int lB = lA + 128;                    // 128..255 / 384..511
        bool vB = lB < 500;
        unsigned ilA = sh_idx[rbase + lA];
        unsigned ilB = sh_idx[rbase + (vB ? lB : lA)];
        const float4* sA = (const float4*)(scores + ((size_t)b * NPB + ilA) * NCLS);
        const float4* sB = (const float4*)(scores + ((size_t)b * NPB + ilB) * NCLS);
        float4 a0 = __ldg(sA + q);
        float4 b0 = __ldg(sB + q);
        float4 a1 = __ldg(sA + q + 8);
        float4 b1 = __ldg(sB + q + 8);
        float4 a2, b2;
        if (q < 4) { a2 = __ldg(sA + 16 + q); b2 = __ldg(sB + 16 + q); }

        int rowA = rbase + lA;
        float4* dA = (float4*)(out + ((size_t)b * KSEL + rowA) * NCLS);
        dA[q]     = a0;
        dA[q + 8] = a1;
        if (q < 4) dA[16 + q] = a2;
        if (vB) {
            int rowB = rbase + lB;
            float4* dB = (float4*)(out + ((size_t)b * KSEL + rowB) * NCLS);
            dB[q]     = b0;
            dB[q + 8] = b1;
            if (q < 4) dB[16 + q] = b2;
        }
    }
    // boxes + batch index: one thread per row (500 rows per CTA)
    if (tid < 500) {
        int row = rbase + tid;
        unsigned il = sh_idx[row];
        size_t g = (size_t)b * NPB + il;
        size_t r = (size_t)b * KSEL + (size_t)row;
        float4 bx = __ldg((const float4*)(boxes + g * 4));
        *(float4*)(out + BX_FOFF + r * 4) = bx;
        out[BI_FOFF + r] = (float)b;
    }
}

extern "C" void kernel_launch(void* const* d_in, const int* in_sizes, int n_in,
                              void* d_out, int out_size)
{
    const float* scores = (const float*)d_in[0];
    const float* boxes  = (const float*)d_in[2];
    float* out = (float*)d_out;

    half_select_kernel<<<2 * BATCH, 1024>>>(scores);
    merge_gather_kernel<<<2 * BATCH, 1024>>>(scores, boxes, out);
}